// round 3
// baseline (speedup 1.0000x reference)
#include <cuda_runtime.h>
#include <cuda_bf16.h>
#include <math.h>

// Problem constants
#define BB   8
#define CC   256
#define HW   40000          // 200*200
#define HW4  10000          // HW / 4
#define KK   8000           // int(0.2 * HW)

// Scratch (allocation-free rule: __device__ globals)
__device__ unsigned g_score_u[BB * HW];   // float bits of sum(x^2) (nonneg -> uint order == float order)
__device__ float    g_sim[BB * HW];       // per-pixel cosine similarity
__device__ double   g_bsum[BB];           // per-batch sum of selected sims

// ---------------------------------------------------------------------------
// Kernel 1: fused per-pixel channel statistics -> score + cosine sim.
// 2-way channel split for occupancy: each block = 128 float4-pixel-groups
// x 2 channel-halves (128 channels each). 625 blocks -> ~4.2 CTAs/SM.
// ---------------------------------------------------------------------------
__global__ void __launch_bounds__(256) k_stats(const float* __restrict__ bev,
                                               const float* __restrict__ pri) {
    // 80000 float4-groups total = 625 blocks * 128 (exact)
    int p    = threadIdx.x & 127;       // pixel-group slot within block
    int half = threadIdx.x >> 7;        // channel half (0 or 1)
    int idx  = blockIdx.x * 128 + p;    // global float4-group index
    int b    = idx / HW4;
    int p4   = idx - b * HW4;

    const float4* pb = reinterpret_cast<const float4*>(bev + (size_t)b * CC * HW) + p4;
    const float4* pp = reinterpret_cast<const float4*>(pri + (size_t)b * CC * HW) + p4;

    float4 sb  = {0.f, 0.f, 0.f, 0.f};
    float4 sp  = {0.f, 0.f, 0.f, 0.f};
    float4 sbb = {0.f, 0.f, 0.f, 0.f};
    float4 spp = {0.f, 0.f, 0.f, 0.f};
    float4 sbp = {0.f, 0.f, 0.f, 0.f};

    int c0 = half * 128;
#pragma unroll 4
    for (int c = c0; c < c0 + 128; c++) {
        float4 x = __ldg(pb + c * HW4);
        float4 y = __ldg(pp + c * HW4);
#define ACC(f)                                \
        sb.f  += x.f;                         \
        sp.f  += y.f;                         \
        sbb.f  = fmaf(x.f, x.f, sbb.f);       \
        spp.f  = fmaf(y.f, y.f, spp.f);       \
        sbp.f  = fmaf(x.f, y.f, sbp.f);
        ACC(x) ACC(y) ACC(z) ACC(w)
#undef ACC
    }

    // combine the two channel-halves through shared memory
    __shared__ float4 sm_sb[128], sm_sp[128], sm_sbb[128], sm_spp[128], sm_sbp[128];
    if (half == 1) {
        sm_sb[p] = sb; sm_sp[p] = sp; sm_sbb[p] = sbb; sm_spp[p] = spp; sm_sbp[p] = sbp;
    }
    __syncthreads();
    if (half == 1) return;

    {
        float4 t;
        t = sm_sb[p];  sb.x += t.x;  sb.y += t.y;  sb.z += t.z;  sb.w += t.w;
        t = sm_sp[p];  sp.x += t.x;  sp.y += t.y;  sp.z += t.z;  sp.w += t.w;
        t = sm_sbb[p]; sbb.x += t.x; sbb.y += t.y; sbb.z += t.z; sbb.w += t.w;
        t = sm_spp[p]; spp.x += t.x; spp.y += t.y; spp.z += t.z; spp.w += t.w;
        t = sm_sbp[p]; sbp.x += t.x; sbp.y += t.y; sbp.z += t.z; sbp.w += t.w;
    }

    const float invC  = 1.0f / (float)CC;
    const float invC1 = 1.0f / (float)(CC - 1);
    int obase = b * HW + p4 * 4;

#define EMIT(f, j) {                                                        \
        float Sb = sb.f, Sp = sp.f, Sb2 = sbb.f, Sp2 = spp.f, Sxp = sbp.f;  \
        float SSb = fmaxf(Sb2 - Sb * Sb * invC, 0.0f);                      \
        float SSp = fmaxf(Sp2 - Sp * Sp * invC, 0.0f);                      \
        float Cov = Sxp - Sb * Sp * invC;                                   \
        float sgb = sqrtf(SSb * invC1) + 1e-6f;                             \
        float sgp = sqrtf(SSp * invC1) + 1e-6f;                             \
        float na  = sqrtf(SSb) / sgb;                                       \
        float nb  = sqrtf(SSp) / sgp;                                       \
        float sim = (Cov / (sgb * sgp)) /                                   \
                    (fmaxf(na, 1e-8f) * fmaxf(nb, 1e-8f));                  \
        g_score_u[obase + j] = __float_as_uint(Sb2);                        \
        g_sim[obase + j]     = sim;                                         \
    }
    EMIT(x, 0) EMIT(y, 1) EMIT(z, 2) EMIT(w, 3)
#undef EMIT
}

// ---------------------------------------------------------------------------
// Kernel 2 (fused): exact k-th largest per batch via 4-pass 8-bit radix
// select (warp-aggregated histogram atomics — scores concentrate in very few
// bins, so per-element smem atomics would serialize), then sum sims over the
// top-k in the same block. One block per batch, 1024 threads.
// ---------------------------------------------------------------------------
__global__ void __launch_bounds__(1024) k_select_sum() {
    int b = blockIdx.x;
    const unsigned* s   = g_score_u + b * HW;
    const float*    sim = g_sim     + b * HW;

    __shared__ unsigned hist[256];
    __shared__ unsigned sh_prefix;
    __shared__ int sh_k;
    __shared__ int sh_tie;
    __shared__ float red[32];

    const int lane = threadIdx.x & 31;
    const int wid  = threadIdx.x >> 5;
    const int ITERS = (HW + 1023) / 1024;   // 40 (last partial)

    if (threadIdx.x == 0) { sh_prefix = 0u; sh_k = KK; sh_tie = 0; }
    __syncthreads();

    // ---- radix select: find k-th largest score bit pattern ----
    for (int pass = 0; pass < 4; pass++) {
        int shift = 24 - 8 * pass;
        unsigned mask = (pass == 0) ? 0u : (0xFFFFFFFFu << (shift + 8));
        if (threadIdx.x < 256) hist[threadIdx.x] = 0u;
        __syncthreads();
        unsigned prefix = sh_prefix;
#pragma unroll 4
        for (int it = 0; it < ITERS; it++) {
            int i = it * 1024 + threadIdx.x;
            unsigned bin = 0xFFFFFFFFu;          // dummy: no contribution
            if (i < HW) {
                unsigned u = s[i];
                if ((u & mask) == prefix) bin = (u >> shift) & 255u;
            }
            // warp-aggregated atomic: one add per distinct bin per warp
            unsigned m = __match_any_sync(0xFFFFFFFFu, bin);
            if (bin != 0xFFFFFFFFu) {
                int leader = __ffs(m) - 1;
                if (lane == leader) atomicAdd(&hist[bin], (unsigned)__popc(m));
            }
        }
        __syncthreads();
        if (threadIdx.x == 0) {
            int kk = sh_k;
            int bin = 255;
            for (; bin > 0; bin--) {
                int c = (int)hist[bin];
                if (kk <= c) break;
                kk -= c;
            }
            sh_prefix = prefix | ((unsigned)bin << shift);
            sh_k = kk;
        }
        __syncthreads();
    }

    unsigned T = sh_prefix;
    int needed = sh_k;

    // ---- sum sims over top-k (score > T always; ties at T up to 'needed') ----
    float local = 0.0f;
#pragma unroll 4
    for (int it = 0; it < ITERS; it++) {
        int i = it * 1024 + threadIdx.x;
        if (i < HW) {
            unsigned u = s[i];
            if (u > T) {
                local += sim[i];
            } else if (u == T) {
                int pos = atomicAdd(&sh_tie, 1);
                if (pos < needed) local += sim[i];
            }
        }
    }

    // block reduction: warp shuffle then cross-warp via shared
    for (int off = 16; off > 0; off >>= 1)
        local += __shfl_down_sync(0xFFFFFFFFu, local, off);
    if (lane == 0) red[wid] = local;
    __syncthreads();
    if (wid == 0) {
        float v = red[lane];
        for (int off = 16; off > 0; off >>= 1)
            v += __shfl_down_sync(0xFFFFFFFFu, v, off);
        if (lane == 0) g_bsum[b] = (double)v;
    }
}

// ---------------------------------------------------------------------------
// Kernel 3: finalize -> scalar loss
// ---------------------------------------------------------------------------
__global__ void k_finalize(const float* __restrict__ dx,
                           const float* __restrict__ dy,
                           const float* __restrict__ dt,
                           float* __restrict__ out) {
    if (threadIdx.x == 0 && blockIdx.x == 0) {
        double total = 0.0;
        for (int i = 0; i < BB; i++) total += g_bsum[i];
        double mean_sim = total / (double)(BB * KK);
        float align = (float)(1.0 - mean_sim);
        float r1 = 0.f, r2 = 0.f;
        for (int i = 0; i < BB; i++) {
            r1 += dx[i] * dx[i] + dy[i] * dy[i];
            r2 += dt[i] * dt[i];
        }
        float reg = r1 * (1.0f / BB) + r2 * (1.0f / BB);
        out[0] = align + 0.1f * reg;
    }
}

extern "C" void kernel_launch(void* const* d_in, const int* in_sizes, int n_in,
                              void* d_out, int out_size) {
    const float* bev = (const float*)d_in[0];
    const float* pri = (const float*)d_in[1];
    const float* dx  = (const float*)d_in[2];
    const float* dy  = (const float*)d_in[3];
    const float* dt  = (const float*)d_in[4];
    float* out = (float*)d_out;

    k_stats<<<625, 256>>>(bev, pri);      // 80000 groups / 128 per block

    k_select_sum<<<BB, 1024>>>();

    k_finalize<<<1, 32>>>(dx, dy, dt, out);
}

// round 4
// speedup vs baseline: 1.2554x; 1.2554x over previous
#include <cuda_runtime.h>
#include <cuda_bf16.h>
#include <math.h>

// Problem constants
#define BB   8
#define CC   256
#define HW   40000          // 200*200
#define HW4  10000          // HW / 4
#define KK   8000           // int(0.2 * HW)

// Scratch (allocation-free rule: __device__ globals)
__device__ unsigned g_score_u[BB * HW];   // float bits of sum(x^2) (nonneg -> uint order == float order)
__device__ float    g_sim[BB * HW];       // per-pixel cosine similarity
__device__ double   g_bsum[BB];           // per-batch sum of selected sims

// ---------------------------------------------------------------------------
// Kernel 1: fused per-pixel channel statistics -> score + cosine sim.
// One thread per float4 of pixels, full 256-channel loop (R2 structure —
// the channel-split variant regressed). unroll 8 => 16 LDG.128 in flight
// per warp body for higher per-warp MLP.
// ---------------------------------------------------------------------------
__global__ void __launch_bounds__(256) k_stats(const float* __restrict__ bev,
                                               const float* __restrict__ pri) {
    int idx = blockIdx.x * blockDim.x + threadIdx.x;
    if (idx >= BB * HW4) return;
    int b  = idx / HW4;
    int p4 = idx - b * HW4;

    const float4* pb = reinterpret_cast<const float4*>(bev + (size_t)b * CC * HW) + p4;
    const float4* pp = reinterpret_cast<const float4*>(pri + (size_t)b * CC * HW) + p4;

    float4 sb  = {0.f, 0.f, 0.f, 0.f};
    float4 sp  = {0.f, 0.f, 0.f, 0.f};
    float4 sbb = {0.f, 0.f, 0.f, 0.f};
    float4 spp = {0.f, 0.f, 0.f, 0.f};
    float4 sbp = {0.f, 0.f, 0.f, 0.f};

#pragma unroll 8
    for (int c = 0; c < CC; c++) {
        float4 x = __ldg(pb + c * HW4);
        float4 y = __ldg(pp + c * HW4);
#define ACC(f)                                \
        sb.f  += x.f;                         \
        sp.f  += y.f;                         \
        sbb.f  = fmaf(x.f, x.f, sbb.f);       \
        spp.f  = fmaf(y.f, y.f, spp.f);       \
        sbp.f  = fmaf(x.f, y.f, sbp.f);
        ACC(x) ACC(y) ACC(z) ACC(w)
#undef ACC
    }

    const float invC  = 1.0f / (float)CC;
    const float invC1 = 1.0f / (float)(CC - 1);
    int obase = b * HW + p4 * 4;

#define EMIT(f, j) {                                                        \
        float Sb = sb.f, Sp = sp.f, Sb2 = sbb.f, Sp2 = spp.f, Sxp = sbp.f;  \
        float SSb = fmaxf(Sb2 - Sb * Sb * invC, 0.0f);                      \
        float SSp = fmaxf(Sp2 - Sp * Sp * invC, 0.0f);                      \
        float Cov = Sxp - Sb * Sp * invC;                                   \
        float sgb = sqrtf(SSb * invC1) + 1e-6f;                             \
        float sgp = sqrtf(SSp * invC1) + 1e-6f;                             \
        float na  = sqrtf(SSb) / sgb;                                       \
        float nb  = sqrtf(SSp) / sgp;                                       \
        float sim = (Cov / (sgb * sgp)) /                                   \
                    (fmaxf(na, 1e-8f) * fmaxf(nb, 1e-8f));                  \
        g_score_u[obase + j] = __float_as_uint(Sb2);                        \
        g_sim[obase + j]     = sim;                                         \
    }
    EMIT(x, 0) EMIT(y, 1) EMIT(z, 2) EMIT(w, 3)
#undef EMIT
}

// ---------------------------------------------------------------------------
// Kernel 2 (fused): exact k-th largest per batch via 4-pass 8-bit radix
// select, then sum sims over the top-k. One block per batch, 1024 threads.
// Histogram is privatized 8 ways (one copy per 4-warp group) because the
// scores concentrate in very few bins (all share exponent byte 0x43), which
// serialized a single shared histogram in earlier rounds.
// ---------------------------------------------------------------------------
__global__ void __launch_bounds__(1024) k_select_sum() {
    int b = blockIdx.x;
    const unsigned* s   = g_score_u + b * HW;
    const float*    sim = g_sim     + b * HW;

    __shared__ unsigned hist8[8][256];   // privatized copies
    __shared__ unsigned hist[256];       // merged
    __shared__ unsigned sh_prefix;
    __shared__ int sh_k;
    __shared__ int sh_tie;
    __shared__ float red[32];

    const int lane = threadIdx.x & 31;
    const int wid  = threadIdx.x >> 5;
    const int grp  = wid >> 2;           // 0..7

    if (threadIdx.x == 0) { sh_prefix = 0u; sh_k = KK; sh_tie = 0; }
    __syncthreads();

    // ---- radix select: find k-th largest score bit pattern ----
    for (int pass = 0; pass < 4; pass++) {
        int shift = 24 - 8 * pass;
        unsigned mask = (pass == 0) ? 0u : (0xFFFFFFFFu << (shift + 8));
        // zero privatized histograms (2048 words / 1024 threads)
        hist8[threadIdx.x >> 8][threadIdx.x & 255] = 0u;
        hist8[(threadIdx.x >> 8) + 4][threadIdx.x & 255] = 0u;
        __syncthreads();
        unsigned prefix = sh_prefix;
        for (int i = threadIdx.x; i < HW; i += 1024) {
            unsigned u = s[i];
            if ((u & mask) == prefix)
                atomicAdd(&hist8[grp][(u >> shift) & 255u], 1u);
        }
        __syncthreads();
        // merge 8 copies -> hist
        if (threadIdx.x < 256) {
            unsigned t = 0;
#pragma unroll
            for (int g = 0; g < 8; g++) t += hist8[g][threadIdx.x];
            hist[threadIdx.x] = t;
        }
        __syncthreads();
        if (threadIdx.x == 0) {
            int kk = sh_k;
            int bin = 255;
            for (; bin > 0; bin--) {
                int c = (int)hist[bin];
                if (kk <= c) break;
                kk -= c;
            }
            sh_prefix = prefix | ((unsigned)bin << shift);
            sh_k = kk;
        }
        __syncthreads();
    }

    unsigned T = sh_prefix;
    int needed = sh_k;

    // ---- sum sims over top-k (score > T always; ties at T up to 'needed') ----
    float local = 0.0f;
    for (int i = threadIdx.x; i < HW; i += 1024) {
        unsigned u = s[i];
        if (u > T) {
            local += sim[i];
        } else if (u == T) {
            int pos = atomicAdd(&sh_tie, 1);
            if (pos < needed) local += sim[i];
        }
    }

    // block reduction: warp shuffle then cross-warp via shared
    for (int off = 16; off > 0; off >>= 1)
        local += __shfl_down_sync(0xFFFFFFFFu, local, off);
    if (lane == 0) red[wid] = local;
    __syncthreads();
    if (wid == 0) {
        float v = red[lane];
        for (int off = 16; off > 0; off >>= 1)
            v += __shfl_down_sync(0xFFFFFFFFu, v, off);
        if (lane == 0) g_bsum[b] = (double)v;
    }
}

// ---------------------------------------------------------------------------
// Kernel 3: finalize -> scalar loss
// ---------------------------------------------------------------------------
__global__ void k_finalize(const float* __restrict__ dx,
                           const float* __restrict__ dy,
                           const float* __restrict__ dt,
                           float* __restrict__ out) {
    if (threadIdx.x == 0 && blockIdx.x == 0) {
        double total = 0.0;
        for (int i = 0; i < BB; i++) total += g_bsum[i];
        double mean_sim = total / (double)(BB * KK);
        float align = (float)(1.0 - mean_sim);
        float r1 = 0.f, r2 = 0.f;
        for (int i = 0; i < BB; i++) {
            r1 += dx[i] * dx[i] + dy[i] * dy[i];
            r2 += dt[i] * dt[i];
        }
        float reg = r1 * (1.0f / BB) + r2 * (1.0f / BB);
        out[0] = align + 0.1f * reg;
    }
}

extern "C" void kernel_launch(void* const* d_in, const int* in_sizes, int n_in,
                              void* d_out, int out_size) {
    const float* bev = (const float*)d_in[0];
    const float* pri = (const float*)d_in[1];
    const float* dx  = (const float*)d_in[2];
    const float* dy  = (const float*)d_in[3];
    const float* dt  = (const float*)d_in[4];
    float* out = (float*)d_out;

    int total = BB * HW4;                 // 80000 threads
    int blocks = (total + 255) / 256;     // 313 blocks
    k_stats<<<blocks, 256>>>(bev, pri);

    k_select_sum<<<BB, 1024>>>();

    k_finalize<<<1, 32>>>(dx, dy, dt, out);
}

// round 5
// speedup vs baseline: 1.4633x; 1.1656x over previous
#include <cuda_runtime.h>
#include <cuda_bf16.h>
#include <math.h>

// Problem constants
#define BB   8
#define CC   256
#define HW   40000          // 200*200
#define HW4  10000          // HW / 4
#define KK   8000           // int(0.2 * HW)

// Scratch (allocation-free rule: __device__ globals)
__device__ unsigned g_score_u[BB * HW];   // float bits of sum(x^2) (nonneg -> uint order == float order)
__device__ float    g_sim[BB * HW];       // per-pixel cosine similarity
__device__ double   g_bsum[BB];           // per-batch sum of selected sims

// ---------------------------------------------------------------------------
// Kernel 1: fused per-pixel channel statistics -> score + cosine sim.
// Exact R2 structure (known 109us @ DRAM 76%): one thread per float4 of
// pixels, 256-channel loop, unroll 4.
// ---------------------------------------------------------------------------
__global__ void __launch_bounds__(256) k_stats(const float* __restrict__ bev,
                                               const float* __restrict__ pri) {
    int idx = blockIdx.x * blockDim.x + threadIdx.x;
    if (idx >= BB * HW4) return;
    int b  = idx / HW4;
    int p4 = idx - b * HW4;

    const float4* pb = reinterpret_cast<const float4*>(bev + (size_t)b * CC * HW) + p4;
    const float4* pp = reinterpret_cast<const float4*>(pri + (size_t)b * CC * HW) + p4;

    float4 sb  = {0.f, 0.f, 0.f, 0.f};
    float4 sp  = {0.f, 0.f, 0.f, 0.f};
    float4 sbb = {0.f, 0.f, 0.f, 0.f};
    float4 spp = {0.f, 0.f, 0.f, 0.f};
    float4 sbp = {0.f, 0.f, 0.f, 0.f};

#pragma unroll 4
    for (int c = 0; c < CC; c++) {
        float4 x = __ldg(pb + c * HW4);
        float4 y = __ldg(pp + c * HW4);
#define ACC(f)                                \
        sb.f  += x.f;                         \
        sp.f  += y.f;                         \
        sbb.f  = fmaf(x.f, x.f, sbb.f);       \
        spp.f  = fmaf(y.f, y.f, spp.f);       \
        sbp.f  = fmaf(x.f, y.f, sbp.f);
        ACC(x) ACC(y) ACC(z) ACC(w)
#undef ACC
    }

    const float invC  = 1.0f / (float)CC;
    const float invC1 = 1.0f / (float)(CC - 1);
    int obase = b * HW + p4 * 4;

#define EMIT(f, j) {                                                        \
        float Sb = sb.f, Sp = sp.f, Sb2 = sbb.f, Sp2 = spp.f, Sxp = sbp.f;  \
        float SSb = fmaxf(Sb2 - Sb * Sb * invC, 0.0f);                      \
        float SSp = fmaxf(Sp2 - Sp * Sp * invC, 0.0f);                      \
        float Cov = Sxp - Sb * Sp * invC;                                   \
        float sgb = sqrtf(SSb * invC1) + 1e-6f;                             \
        float sgp = sqrtf(SSp * invC1) + 1e-6f;                             \
        float na  = sqrtf(SSb) / sgb;                                       \
        float nb  = sqrtf(SSp) / sgp;                                       \
        float sim = (Cov / (sgb * sgp)) /                                   \
                    (fmaxf(na, 1e-8f) * fmaxf(nb, 1e-8f));                  \
        g_score_u[obase + j] = __float_as_uint(Sb2);                        \
        g_sim[obase + j]     = sim;                                         \
    }
    EMIT(x, 0) EMIT(y, 1) EMIT(z, 2) EMIT(w, 3)
#undef EMIT
}

// ---------------------------------------------------------------------------
// Kernel 2 (fused): exact k-th largest per batch via 4-pass 8-bit radix
// select + top-k sim sum. One block per batch, 1024 threads.
// All 40000 scores are cached in 160KB dynamic smem with ONE batched
// vectorized global sweep (the R2/R4 versions re-read global 5x with
// atomic-fenced scalar loads at DRAM latency -> ~40us tail).
// ---------------------------------------------------------------------------
__global__ void __launch_bounds__(1024) k_select_sum() {
    extern __shared__ unsigned sc[];     // 40000 score words (160 KB)
    int b = blockIdx.x;
    const uint4*  s4   = reinterpret_cast<const uint4*>(g_score_u + b * HW);
    const float4* sim4 = reinterpret_cast<const float4*>(g_sim + b * HW);
    uint4* sc4 = reinterpret_cast<uint4*>(sc);

    __shared__ unsigned hist8[8][256];   // privatized histogram copies
    __shared__ unsigned hist[256];       // merged
    __shared__ unsigned sh_prefix;
    __shared__ int sh_k;
    __shared__ int sh_tie;
    __shared__ float red[32];

    const int tid  = threadIdx.x;
    const int lane = tid & 31;
    const int wid  = tid >> 5;
    const int grp  = wid >> 2;           // 0..7

    if (tid == 0) { sh_prefix = 0u; sh_k = KK; sh_tie = 0; }

    // ---- load all scores into smem (coalesced uint4, independent loads) ----
    for (int i = tid; i < HW4; i += 1024)
        sc4[i] = s4[i];
    __syncthreads();

    // ---- radix select over smem-resident scores ----
    for (int pass = 0; pass < 4; pass++) {
        int shift = 24 - 8 * pass;
        unsigned mask = (pass == 0) ? 0u : (0xFFFFFFFFu << (shift + 8));
        hist8[tid >> 8][tid & 255] = 0u;
        hist8[(tid >> 8) + 4][tid & 255] = 0u;
        __syncthreads();
        unsigned prefix = sh_prefix;
        for (int i = tid; i < HW; i += 1024) {
            unsigned u = sc[i];
            if ((u & mask) == prefix)
                atomicAdd(&hist8[grp][(u >> shift) & 255u], 1u);
        }
        __syncthreads();
        if (tid < 256) {
            unsigned t = 0;
#pragma unroll
            for (int g = 0; g < 8; g++) t += hist8[g][tid];
            hist[tid] = t;
        }
        __syncthreads();
        if (tid == 0) {
            int kk = sh_k;
            int bin = 255;
            for (; bin > 0; bin--) {
                int c = (int)hist[bin];
                if (kk <= c) break;
                kk -= c;
            }
            sh_prefix = prefix | ((unsigned)bin << shift);
            sh_k = kk;
        }
        __syncthreads();
    }

    unsigned T = sh_prefix;
    int needed = sh_k;

    // ---- sum sims over top-k: vectorized global sim loads + smem scores ----
    float local = 0.0f;
    for (int i = tid; i < HW4; i += 1024) {
        float4 sm = sim4[i];          // independent 128-bit loads, high MLP
        uint4  u  = sc4[i];
#define SEL(f, j) {                                                 \
            unsigned uu = u.f;                                      \
            if (uu > T) {                                           \
                local += sm.j;                                      \
            } else if (uu == T) {                                   \
                int pos = atomicAdd(&sh_tie, 1);                    \
                if (pos < needed) local += sm.j;                    \
            }                                                       \
        }
        SEL(x, x) SEL(y, y) SEL(z, z) SEL(w, w)
#undef SEL
    }

    // block reduction
    for (int off = 16; off > 0; off >>= 1)
        local += __shfl_down_sync(0xFFFFFFFFu, local, off);
    if (lane == 0) red[wid] = local;
    __syncthreads();
    if (wid == 0) {
        float v = red[lane];
        for (int off = 16; off > 0; off >>= 1)
            v += __shfl_down_sync(0xFFFFFFFFu, v, off);
        if (lane == 0) g_bsum[b] = (double)v;
    }
}

// ---------------------------------------------------------------------------
// Kernel 3: finalize -> scalar loss
// ---------------------------------------------------------------------------
__global__ void k_finalize(const float* __restrict__ dx,
                           const float* __restrict__ dy,
                           const float* __restrict__ dt,
                           float* __restrict__ out) {
    if (threadIdx.x == 0 && blockIdx.x == 0) {
        double total = 0.0;
        for (int i = 0; i < BB; i++) total += g_bsum[i];
        double mean_sim = total / (double)(BB * KK);
        float align = (float)(1.0 - mean_sim);
        float r1 = 0.f, r2 = 0.f;
        for (int i = 0; i < BB; i++) {
            r1 += dx[i] * dx[i] + dy[i] * dy[i];
            r2 += dt[i] * dt[i];
        }
        float reg = r1 * (1.0f / BB) + r2 * (1.0f / BB);
        out[0] = align + 0.1f * reg;
    }
}

extern "C" void kernel_launch(void* const* d_in, const int* in_sizes, int n_in,
                              void* d_out, int out_size) {
    const float* bev = (const float*)d_in[0];
    const float* pri = (const float*)d_in[1];
    const float* dx  = (const float*)d_in[2];
    const float* dy  = (const float*)d_in[3];
    const float* dt  = (const float*)d_in[4];
    float* out = (float*)d_out;

    int total = BB * HW4;                 // 80000 threads
    int blocks = (total + 255) / 256;     // 313 blocks
    k_stats<<<blocks, 256>>>(bev, pri);

    const int SMEM_SEL = HW * (int)sizeof(unsigned);   // 160000 B
    cudaFuncSetAttribute(k_select_sum,
                         cudaFuncAttributeMaxDynamicSharedMemorySize, SMEM_SEL);
    k_select_sum<<<BB, 1024, SMEM_SEL>>>();

    k_finalize<<<1, 32>>>(dx, dy, dt, out);
}